// round 12
// baseline (speedup 1.0000x reference)
#include <cuda_runtime.h>
#include <math.h>
#include <stdint.h>

#define L_DIM 16384
#define Q_DIM (L_DIM / 4)          // 4096 float4 per row
#define B_DIM 64
#define N_ROWS 1024
#define TOTAL_BLOCKS (N_ROWS + B_DIM)   // 1088
#define THREADS 256
#define CHUNK_BYTES 8192
#define CHUNK_Q (CHUNK_BYTES / 16)      // 512 quads per chunk
#define QPT (CHUNK_Q / THREADS)         // 2 quads / thread / chunk
#define NCHUNK ((L_DIM * 4) / CHUNK_BYTES)  // 8 chunks per 64KB row
#define STAGES 3
#define CAP 768
#define THR_FIXED 2.25f            // speculative gather threshold (N(0,1) logits)

// Scratch (allocation-free rule: __device__ globals)
__device__ float g_nmask[B_DIM];
__device__ float g_sp2[N_ROWS];
__device__ float g_spm[N_ROWS];
__device__ unsigned int g_done = 0;

// ---- minimal TMA / mbarrier helpers ----
__device__ __forceinline__ uint32_t smem_u32(const void* p) {
    return (uint32_t)__cvta_generic_to_shared(p);
}
__device__ __forceinline__ void mbar_init(uint32_t mbar, uint32_t cnt) {
    asm volatile("mbarrier.init.shared.b64 [%0], %1;" :: "r"(mbar), "r"(cnt) : "memory");
}
__device__ __forceinline__ void mbar_expect_tx(uint32_t mbar, uint32_t bytes) {
    asm volatile("mbarrier.arrive.expect_tx.shared.b64 _, [%0], %1;"
                 :: "r"(mbar), "r"(bytes) : "memory");
}
__device__ __forceinline__ void bulk_g2s(uint32_t dst, const void* src, uint32_t bytes, uint32_t mbar) {
    asm volatile("cp.async.bulk.shared::cluster.global.mbarrier::complete_tx::bytes [%0], [%1], %2, [%3];"
                 :: "r"(dst), "l"(src), "r"(bytes), "r"(mbar) : "memory");
}
__device__ __forceinline__ void mbar_wait(uint32_t mbar, uint32_t parity) {
    asm volatile(
        "{\n\t"
        ".reg .pred P;\n\t"
        "WAIT_%=:\n\t"
        "mbarrier.try_wait.parity.acquire.cta.shared::cta.b64 P, [%0], %1, 0x989680;\n\t"
        "@P bra DONE_%=;\n\t"
        "bra WAIT_%=;\n\t"
        "DONE_%=:\n\t"
        "}"
        :: "r"(mbar), "r"(parity) : "memory");
}

__global__ void __launch_bounds__(THREADS) fused_kernel(
    const float* __restrict__ logits,
    const float* __restrict__ mask,
    float* __restrict__ out)
{
    __shared__ __align__(16) char ring[STAGES * CHUNK_BYTES];   // 24 KB
    __shared__ __align__(8)  unsigned long long mbar_storage[STAGES];
    __shared__ float sval[CAP];
    __shared__ int   sidx[CAP];
    __shared__ int   s_cnt;
    __shared__ float s_red[THREADS / 32];
    __shared__ float s_max;
    __shared__ float s_fin[THREADS];
    __shared__ unsigned int s_ticket;

    const int blk  = blockIdx.x;
    const int tid  = threadIdx.x;
    const int warp = tid >> 5, lane = tid & 31;
    const bool is_row = (blk < N_ROWS);

    const float* src_row = is_row ? (logits + (size_t)blk * L_DIM)
                                  : (mask + (size_t)(blk - N_ROWS) * L_DIM);

    // ---- init mbarriers + prime the TMA pipeline ----
    if (tid == 0) {
        #pragma unroll
        for (int s = 0; s < STAGES; s++) mbar_init(smem_u32(&mbar_storage[s]), 1);
        s_cnt = 0;
    }
    __syncthreads();
    if (tid == 0) {
        #pragma unroll
        for (int c = 0; c < STAGES; c++) {
            uint32_t mb = smem_u32(&mbar_storage[c]);
            mbar_expect_tx(mb, CHUNK_BYTES);
            bulk_g2s(smem_u32(ring + c * CHUNK_BYTES),
                     src_row + c * (CHUNK_BYTES / 4), CHUNK_BYTES, mb);
        }
    }

    // ---- streamed consume: TMA engine owns DRAM; 8 warps drain smem ----
    float m0 = -3.4e38f, m1 = -3.4e38f;   // two independent max chains
    float msum = 0.f;
    for (int c = 0; c < NCHUNK; c++) {
        const int s = c % STAGES;
        const uint32_t p = (c / STAGES) & 1u;
        mbar_wait(smem_u32(&mbar_storage[s]), p);

        const float4* cq = (const float4*)(ring + s * CHUNK_BYTES);
        if (is_row) {
            // QPT == 2: two quads per thread per chunk, independent chains
            float4 v0 = cq[tid];
            float4 v1 = cq[tid + THREADS];
            float vm0 = fmaxf(fmaxf(v0.x, v0.y), fmaxf(v0.z, v0.w));
            float vm1 = fmaxf(fmaxf(v1.x, v1.y), fmaxf(v1.z, v1.w));
            m0 = fmaxf(m0, vm0);
            m1 = fmaxf(m1, vm1);
            if (vm0 > THR_FIXED) {
                int qi = c * CHUNK_Q + tid;
                if (v0.x > THR_FIXED) { int q = atomicAdd(&s_cnt, 1); if (q < CAP) { sval[q] = v0.x; sidx[q] = 4 * qi + 0; } }
                if (v0.y > THR_FIXED) { int q = atomicAdd(&s_cnt, 1); if (q < CAP) { sval[q] = v0.y; sidx[q] = 4 * qi + 1; } }
                if (v0.z > THR_FIXED) { int q = atomicAdd(&s_cnt, 1); if (q < CAP) { sval[q] = v0.z; sidx[q] = 4 * qi + 2; } }
                if (v0.w > THR_FIXED) { int q = atomicAdd(&s_cnt, 1); if (q < CAP) { sval[q] = v0.w; sidx[q] = 4 * qi + 3; } }
            }
            if (vm1 > THR_FIXED) {
                int qi = c * CHUNK_Q + tid + THREADS;
                if (v1.x > THR_FIXED) { int q = atomicAdd(&s_cnt, 1); if (q < CAP) { sval[q] = v1.x; sidx[q] = 4 * qi + 0; } }
                if (v1.y > THR_FIXED) { int q = atomicAdd(&s_cnt, 1); if (q < CAP) { sval[q] = v1.y; sidx[q] = 4 * qi + 1; } }
                if (v1.z > THR_FIXED) { int q = atomicAdd(&s_cnt, 1); if (q < CAP) { sval[q] = v1.z; sidx[q] = 4 * qi + 2; } }
                if (v1.w > THR_FIXED) { int q = atomicAdd(&s_cnt, 1); if (q < CAP) { sval[q] = v1.w; sidx[q] = 4 * qi + 3; } }
            }
        } else {
            float4 v0 = cq[tid];
            float4 v1 = cq[tid + THREADS];
            msum += (v0.x + v0.y) + (v0.z + v0.w) + (v1.x + v1.y) + (v1.z + v1.w);
        }
        __syncthreads();   // all lanes done with stage s
        if (tid == 0 && c + STAGES < NCHUNK) {
            uint32_t mb = smem_u32(&mbar_storage[s]);
            mbar_expect_tx(mb, CHUNK_BYTES);
            bulk_g2s(smem_u32(ring + s * CHUNK_BYTES),
                     src_row + (c + STAGES) * (CHUNK_BYTES / 4), CHUNK_BYTES, mb);
        }
    }

    if (is_row) {
        // ---- block max reduce ----
        float m = fmaxf(m0, m1);
        #pragma unroll
        for (int o = 16; o; o >>= 1) m = fmaxf(m, __shfl_xor_sync(0xffffffffu, m, o));
        if (lane == 0) s_red[warp] = m;
        __syncthreads();
        if (tid == 0) {
            float t = s_red[0];
            #pragma unroll
            for (int w = 1; w < THREADS / 32; w++) t = fmaxf(t, s_red[w]);
            s_max = t;
        }
        __syncthreads();
        const float supp_thr = s_max - 1.0f;        // support ⊆ {z > max-1}
        const bool fb = (supp_thr < THR_FIXED) || (s_cnt >= CAP);
        const int cnt = min(s_cnt, CAP);

        if (warp == 0) {
            const int b = blk >> 4;
            const float* mrow = mask + (size_t)b * L_DIM;
            float sp2 = 0.f, spm = 0.f;

            if (!fb) {
                // ---- Michelot from tau0 = max-1 over smem candidates ----
                float tau = supp_thr;
                for (int iter = 0; iter < 64; iter++) {
                    float s = 0.f; int c2 = 0;
                    for (int i = lane; i < cnt; i += 32) {
                        float v = sval[i];
                        if (v > tau) { s += v; c2++; }
                    }
                    #pragma unroll
                    for (int o = 16; o; o >>= 1) {
                        s  += __shfl_xor_sync(0xffffffffu, s, o);
                        c2 += __shfl_xor_sync(0xffffffffu, c2, o);
                    }
                    float nt = (s - 1.0f) / (float)c2;   // c2 >= 1 (argmax active)
                    if (nt == tau) break;
                    tau = nt;
                }
                for (int i = lane; i < cnt; i += 32) {
                    float p = sval[i] - tau;
                    if (p > 0.f) {
                        sp2 += p * p;
                        spm += mrow[sidx[i]] * p;        // mask is 0/1
                    }
                }
            } else {
                // ---- fallback (P ~ 8e-5/row): exact full-row Michelot from L2 ----
                const float4* z4 = (const float4*)src_row;
                float tau = supp_thr;
                for (int iter = 0; iter < 64; iter++) {
                    float s = 0.f; int c2 = 0;
                    for (int i = lane; i < Q_DIM; i += 32) {
                        float4 q = z4[i];
                        if (q.x > tau) { s += q.x; c2++; }
                        if (q.y > tau) { s += q.y; c2++; }
                        if (q.z > tau) { s += q.z; c2++; }
                        if (q.w > tau) { s += q.w; c2++; }
                    }
                    #pragma unroll
                    for (int o = 16; o; o >>= 1) {
                        s  += __shfl_xor_sync(0xffffffffu, s, o);
                        c2 += __shfl_xor_sync(0xffffffffu, c2, o);
                    }
                    float nt = (s - 1.0f) / (float)c2;
                    if (nt == tau) break;
                    tau = nt;
                }
                for (int i = lane; i < Q_DIM; i += 32) {
                    float4 q = z4[i];
                    float px = q.x - tau, py = q.y - tau, pz = q.z - tau, pw = q.w - tau;
                    if (px > 0.f) { sp2 += px * px; spm += mrow[4 * i + 0] * px; }
                    if (py > 0.f) { sp2 += py * py; spm += mrow[4 * i + 1] * py; }
                    if (pz > 0.f) { sp2 += pz * pz; spm += mrow[4 * i + 2] * pz; }
                    if (pw > 0.f) { sp2 += pw * pw; spm += mrow[4 * i + 3] * pw; }
                }
            }
            #pragma unroll
            for (int o = 16; o; o >>= 1) {
                sp2 += __shfl_xor_sync(0xffffffffu, sp2, o);
                spm += __shfl_xor_sync(0xffffffffu, spm, o);
            }
            if (lane == 0) {
                g_sp2[blk] = sp2;
                g_spm[blk] = spm;
            }
        }
    } else {
        // ---- mask block: sum reduce ----
        #pragma unroll
        for (int o = 16; o; o >>= 1) msum += __shfl_xor_sync(0xffffffffu, msum, o);
        if (lane == 0) s_red[warp] = msum;
        __syncthreads();
        if (tid == 0) {
            float t = 0.f;
            #pragma unroll
            for (int w = 0; w < THREADS / 32; w++) t += s_red[w];
            g_nmask[blk - N_ROWS] = t;
        }
    }

    // ------------- last-block-done final reduction (deterministic) ---------
    __syncthreads();
    __threadfence();
    if (tid == 0) s_ticket = atomicAdd(&g_done, 1u);
    __syncthreads();
    if (s_ticket == TOTAL_BLOCKS - 1) {
        float acc = 0.f;
        #pragma unroll
        for (int j = 0; j < N_ROWS / THREADS; j++) {
            int r = tid + j * THREADS;
            int b = r >> 4;
            float inv_n = 1.0f / fmaxf(g_nmask[b], 1e-12f);
            acc += 0.5f * g_sp2[r] - inv_n * g_spm[r] + 0.5f * inv_n;
        }
        s_fin[tid] = acc;
        __syncthreads();
        #pragma unroll
        for (int o = THREADS / 2; o > 0; o >>= 1) {
            if (tid < o) s_fin[tid] += s_fin[tid + o];
            __syncthreads();
        }
        if (tid == 0) {
            out[0] = s_fin[0] * (1.0f / (float)N_ROWS);
            g_done = 0;        // reset for next graph replay
        }
    }
}

// ---------------------------------------------------------------------------
extern "C" void kernel_launch(void* const* d_in, const int* in_sizes, int n_in,
                              void* d_out, int out_size) {
    const float* logits = (const float*)d_in[0];   // (64,16,16384) fp32
    const float* mask   = (const float*)d_in[1];   // (64,16384) fp32
    float* out = (float*)d_out;

    fused_kernel<<<TOTAL_BLOCKS, THREADS>>>(logits, mask, out);
}

// round 13
// speedup vs baseline: 1.5612x; 1.5612x over previous
#include <cuda_runtime.h>
#include <math.h>
#include <stdint.h>

#define L_DIM 16384
#define Q_DIM (L_DIM / 4)
#define B_DIM 64
#define K_DIM 16
#define N_ROWS 1024
#define MASK_BLOCKS B_DIM
#define TOTAL_BLOCKS (N_ROWS + MASK_BLOCKS)   // 1088
#define THREADS 256
#define ITERS 16                   // quads per thread (256*16 = 4096 = row)
#define DEPTH 4                    // pipeline depth (float4 loads in flight)
#define GROUPS (ITERS / DEPTH)     // 4
#define CAP 1024
#define THR_FIXED 2.0f             // speculative flag threshold (N(0,1) logits)
#define ROW_BYTES (L_DIM * 4)      // 65536

// Scratch (allocation-free rule: __device__ globals)
__device__ float g_nmask[B_DIM];
__device__ float g_sp2[N_ROWS];
__device__ float g_spm[N_ROWS];
__device__ unsigned int g_done = 0;

// Bulk L2 prefetch: DRAM->L2 streaming handled by the async engine,
// no smem, no mbarrier, purely a hint ahead of the demand LDGs.
__device__ __forceinline__ void prefetch_l2_bulk(const void* gptr, uint32_t bytes) {
    asm volatile("cp.async.bulk.prefetch.L2.global [%0], %1;"
                 :: "l"(gptr), "r"(bytes) : "memory");
}

__global__ void __launch_bounds__(THREADS, 4) fused_kernel(
    const float* __restrict__ logits,
    const float* __restrict__ mask,
    float* __restrict__ out)
{
    __shared__ float sval[CAP];
    __shared__ int   sidx[CAP];
    __shared__ int   s_cnt;
    __shared__ float s_red[THREADS / 32];
    __shared__ float s_max;
    __shared__ float s_fin[THREADS];
    __shared__ unsigned int s_ticket;

    const int blk  = blockIdx.x;
    const int tid  = threadIdx.x;
    const int warp = tid >> 5, lane = tid & 31;

    if (blk >= N_ROWS) {
        // --------- mask-sum block (one per batch row), pipelined ----------
        const int b = blk - N_ROWS;
        const float4* m4 = (const float4*)(mask + (size_t)b * L_DIM);
        if (tid == 0) prefetch_l2_bulk(m4, ROW_BYTES);
        float4 a[DEPTH], nb[DEPTH];
        #pragma unroll
        for (int k = 0; k < DEPTH; k++) a[k] = m4[tid + k * THREADS];
        float s = 0.f;
        #pragma unroll
        for (int g = 0; g < GROUPS; g++) {
            if (g + 1 < GROUPS) {
                #pragma unroll
                for (int k = 0; k < DEPTH; k++) nb[k] = m4[tid + ((g + 1) * DEPTH + k) * THREADS];
            }
            #pragma unroll
            for (int k = 0; k < DEPTH; k++) s += (a[k].x + a[k].y) + (a[k].z + a[k].w);
            #pragma unroll
            for (int k = 0; k < DEPTH; k++) a[k] = nb[k];
        }
        #pragma unroll
        for (int o = 16; o; o >>= 1) s += __shfl_xor_sync(0xffffffffu, s, o);
        if (lane == 0) s_red[warp] = s;
        __syncthreads();
        if (tid == 0) {
            float t = 0.f;
            #pragma unroll
            for (int w = 0; w < THREADS / 32; w++) t += s_red[w];
            g_nmask[b] = t;
        }
    } else {
        // ----------------------- row block (b,k) ---------------------------
        const int row = blk;
        const float4* z4 = (const float4*)(logits + (size_t)row * L_DIM);
        if (tid == 0) {
            prefetch_l2_bulk(z4, ROW_BYTES);   // async engine races ahead into L2
            s_cnt = 0;
        }

        // ---- pass 1: pipelined stream — next DEPTH loads always in flight ----
        float4 a[DEPTH], nb[DEPTH];
        #pragma unroll
        for (int k = 0; k < DEPTH; k++) a[k] = z4[tid + k * THREADS];
        float m = -3.4e38f;
        unsigned int qmask = 0u;
        #pragma unroll
        for (int g = 0; g < GROUPS; g++) {
            if (g + 1 < GROUPS) {
                #pragma unroll
                for (int k = 0; k < DEPTH; k++) nb[k] = z4[tid + ((g + 1) * DEPTH + k) * THREADS];
            }
            #pragma unroll
            for (int k = 0; k < DEPTH; k++) {
                float vm = fmaxf(fmaxf(a[k].x, a[k].y), fmaxf(a[k].z, a[k].w));
                m = fmaxf(m, vm);
                qmask |= (vm > THR_FIXED ? 1u : 0u) << (g * DEPTH + k);
            }
            #pragma unroll
            for (int k = 0; k < DEPTH; k++) a[k] = nb[k];
        }
        #pragma unroll
        for (int o = 16; o; o >>= 1) m = fmaxf(m, __shfl_xor_sync(0xffffffffu, m, o));
        if (lane == 0) s_red[warp] = m;
        __syncthreads();
        if (tid == 0) {
            float t = s_red[0];
            #pragma unroll
            for (int w = 1; w < THREADS / 32; w++) t = fmaxf(t, s_red[w]);
            s_max = t;
        }
        __syncthreads();
        const float supp_thr = s_max - 1.0f;   // support ⊆ {z > max-1}

        if (supp_thr >= THR_FIXED) {
            // ---- pass 2 (fast path): revisit only flagged quads (L1/L2-hot) ----
            unsigned int qm = qmask;
            while (qm) {
                int j = __ffs(qm) - 1;
                qm &= qm - 1u;
                int i = tid + j * THREADS;
                float4 q = z4[i];
                if (q.x > supp_thr) { int p = atomicAdd(&s_cnt, 1); if (p < CAP) { sval[p] = q.x; sidx[p] = 4 * i + 0; } }
                if (q.y > supp_thr) { int p = atomicAdd(&s_cnt, 1); if (p < CAP) { sval[p] = q.y; sidx[p] = 4 * i + 1; } }
                if (q.z > supp_thr) { int p = atomicAdd(&s_cnt, 1); if (p < CAP) { sval[p] = q.z; sidx[p] = 4 * i + 2; } }
                if (q.w > supp_thr) { int p = atomicAdd(&s_cnt, 1); if (p < CAP) { sval[p] = q.w; sidx[p] = 4 * i + 3; } }
            }
            __syncthreads();
        }
        if (supp_thr < THR_FIXED || s_cnt >= CAP) {
            // ---- fallback (≈never): full re-gather from L2 at supp_thr ----
            __syncthreads();
            if (tid == 0) s_cnt = 0;
            __syncthreads();
            #pragma unroll 4
            for (int it = 0; it < ITERS; it++) {
                int i = tid + it * THREADS;
                float4 q = z4[i];
                if (q.x > supp_thr) { int p = atomicAdd(&s_cnt, 1); if (p < CAP) { sval[p] = q.x; sidx[p] = 4 * i + 0; } }
                if (q.y > supp_thr) { int p = atomicAdd(&s_cnt, 1); if (p < CAP) { sval[p] = q.y; sidx[p] = 4 * i + 1; } }
                if (q.z > supp_thr) { int p = atomicAdd(&s_cnt, 1); if (p < CAP) { sval[p] = q.z; sidx[p] = 4 * i + 2; } }
                if (q.w > supp_thr) { int p = atomicAdd(&s_cnt, 1); if (p < CAP) { sval[p] = q.w; sidx[p] = 4 * i + 3; } }
            }
            __syncthreads();
        }
        const int cnt = min(s_cnt, CAP);

        // ---- warp 0: Michelot iteration (start at tau = max-1), loss terms ----
        if (warp == 0) {
            float tau = supp_thr;   // tau* >= max-1; candidate set ⊇ support, nonempty
            for (int iter = 0; iter < 64; iter++) {
                float s = 0.f; int c = 0;
                for (int i = lane; i < cnt; i += 32) {
                    float vv = sval[i];
                    if (vv > tau) { s += vv; c++; }
                }
                #pragma unroll
                for (int o = 16; o; o >>= 1) {
                    s += __shfl_xor_sync(0xffffffffu, s, o);
                    c += __shfl_xor_sync(0xffffffffu, c, o);
                }
                float nt = (s - 1.0f) / (float)c;
                if (nt == tau) break;
                tau = nt;
            }

            const int b = blk >> 4;
            const float* mrow = mask + (size_t)b * L_DIM;
            float sp2 = 0.f, spm = 0.f;
            for (int i = lane; i < cnt; i += 32) {
                float p = sval[i] - tau;
                if (p > 0.f) {
                    sp2 += p * p;
                    spm += mrow[sidx[i]] * p;   // mask is 0/1; inv_n applied at the end
                }
            }
            #pragma unroll
            for (int o = 16; o; o >>= 1) {
                sp2 += __shfl_xor_sync(0xffffffffu, sp2, o);
                spm += __shfl_xor_sync(0xffffffffu, spm, o);
            }
            if (lane == 0) {
                g_sp2[blk] = sp2;
                g_spm[blk] = spm;
            }
        }
    }

    // ------------- last-block-done final reduction (deterministic) ---------
    __syncthreads();
    __threadfence();
    if (tid == 0) s_ticket = atomicAdd(&g_done, 1u);
    __syncthreads();
    if (s_ticket == TOTAL_BLOCKS - 1) {
        float acc = 0.f;
        #pragma unroll
        for (int j = 0; j < N_ROWS / THREADS; j++) {
            int r = tid + j * THREADS;
            int b = r >> 4;
            float inv_n = 1.0f / fmaxf(g_nmask[b], 1e-12f);
            // sum_L (p-q)^2 = sum p^2 - 2*inv_n*spm + 1/n
            acc += 0.5f * g_sp2[r] - inv_n * g_spm[r] + 0.5f * inv_n;
        }
        s_fin[tid] = acc;
        __syncthreads();
        #pragma unroll
        for (int o = THREADS / 2; o > 0; o >>= 1) {
            if (tid < o) s_fin[tid] += s_fin[tid + o];
            __syncthreads();
        }
        if (tid == 0) {
            out[0] = s_fin[0] * (1.0f / (float)N_ROWS);
            g_done = 0;        // reset for next graph replay
        }
    }
}

// ---------------------------------------------------------------------------
extern "C" void kernel_launch(void* const* d_in, const int* in_sizes, int n_in,
                              void* d_out, int out_size) {
    const float* logits = (const float*)d_in[0];   // (64,16,16384) fp32
    const float* mask   = (const float*)d_in[1];   // (64,16384) fp32
    float* out = (float*)d_out;

    fused_kernel<<<TOTAL_BLOCKS, THREADS>>>(logits, mask, out);
}